// round 1
// baseline (speedup 1.0000x reference)
#include <cuda_runtime.h>
#include <cstdint>

#define BB 8
#define CC 64
#define HH 152
#define WW 272
#define HWSZ (HH * WW)      // 41344
#define KK 500
#define TILE 32
#define NTILE 16            // ceil(500/32)

#define ALPHA 0.25f
#define PROB_MIN 1e-4f

// Scratch (no allocations allowed)
__device__ float  g_cur[BB * KK * CC];   // [B,K,C]
__device__ float  g_pre[BB * KK * CC];   // [B,K,C]
__device__ double g_acc = 0.0;
__device__ int    g_is64 = 1;

// ---------------------------------------------------------------------------
// Detect whether index tensors are int64 or int32 (JAX x64 ambiguity).
// If the underlying data were int32, reading as int64 pairs (lo,hi) gives
// values >= 2^32 whenever hi != 0; with 32 random probes the chance of
// misdetection is ~ (1/41344)^32 ~ 0.
// ---------------------------------------------------------------------------
__global__ void detect_kernel(const long long* __restrict__ p)
{
    long long v = p[threadIdx.x];  // 32 probes (first 64 int32 slots; count=4000 so in-bounds)
    unsigned bad = __ballot_sync(0xffffffffu, (v < 0) || (v >= (long long)HWSZ));
    if (threadIdx.x == 0) g_is64 = (bad == 0) ? 1 : 0;
}

// ---------------------------------------------------------------------------
// Masked gather: g_cur[b,k,c] = cur_reid[b, c, idx(b,k)], idx chosen by mask.
// One thread per (b,k,c); c fastest -> coalesced smem-side writes, scattered
// global reads (inherent to the layout, high MLP hides latency).
// ---------------------------------------------------------------------------
__global__ void gather_kernel(const float* __restrict__ cur_reid,
                              const float* __restrict__ pre_reid,
                              const void*  __restrict__ cur_inds,
                              const void*  __restrict__ pre_inds,
                              const void*  __restrict__ cur_cir,
                              const void*  __restrict__ pre_cir,
                              const int*   __restrict__ mask)
{
    int tid = blockIdx.x * blockDim.x + threadIdx.x;
    if (tid >= BB * KK * CC) return;
    int c  = tid & (CC - 1);
    int bk = tid / CC;
    int b  = bk / KK;

    int m = mask[bk];  // tracking_mask[b,k,0]
    int idx_c, idx_p;
    if (g_is64) {
        const long long* ci = (const long long*)cur_inds;
        const long long* pi = (const long long*)pre_inds;
        const long long* cc2 = (const long long*)cur_cir;
        const long long* pc2 = (const long long*)pre_cir;
        idx_c = (int)(m ? ci[bk] : cc2[bk]);
        idx_p = (int)(m ? pi[bk] : pc2[bk]);
    } else {
        const int* ci = (const int*)cur_inds;
        const int* pi = (const int*)pre_inds;
        const int* cc2 = (const int*)cur_cir;
        const int* pc2 = (const int*)pre_cir;
        idx_c = m ? ci[bk] : cc2[bk];
        idx_p = m ? pi[bk] : pc2[bk];
    }

    size_t base = ((size_t)b * CC + c) * (size_t)HWSZ;
    g_cur[tid] = cur_reid[base + idx_c];
    g_pre[tid] = pre_reid[base + idx_p];
}

// ---------------------------------------------------------------------------
// Fused tiled GEMM (cur @ pre^T per batch) + sigmoid + focal loss + reduce.
// Block = 256 threads, 32x32 output tile, 2x2 register micro-tile per thread.
// ---------------------------------------------------------------------------
__device__ __forceinline__ float loss_elem(int b, int i, int j, float dot,
                                           const int* __restrict__ mask)
{
    if (i >= KK || j >= KK) return 0.0f;
    float s = 1.0f / (1.0f + __expf(-dot));
    bool gt = (i == j) && (mask[b * KK + i] != 0);
    float p = gt ? s : (1.0f - s);
    p = fminf(fmaxf(p, PROB_MIN), 1.0f);
    float a = gt ? ALPHA : (1.0f - ALPHA);
    float omp = 1.0f - p;
    return -a * omp * omp * __logf(p);
}

__global__ __launch_bounds__(256)
void loss_kernel(const int* __restrict__ mask)
{
    __shared__ float sc[TILE][CC + 1];  // +1 pad: conflict-free strided reads
    __shared__ float sp[TILE][CC + 1];
    __shared__ float wsum[8];

    int b  = blockIdx.z;
    int i0 = blockIdx.y * TILE;
    int j0 = blockIdx.x * TILE;
    int t  = threadIdx.x;

    // Load tiles (zero-fill out-of-range rows)
    #pragma unroll
    for (int e = t; e < TILE * CC; e += 256) {
        int r = e >> 6;        // /64
        int c = e & 63;
        int gi = i0 + r;
        int gj = j0 + r;
        sc[r][c] = (gi < KK) ? g_cur[((size_t)b * KK + gi) * CC + c] : 0.0f;
        sp[r][c] = (gj < KK) ? g_pre[((size_t)b * KK + gj) * CC + c] : 0.0f;
    }
    __syncthreads();

    int ib = t & 15;   // i offsets: ib, ib+16
    int jb = t >> 4;   // j offsets: jb, jb+16

    float a00 = 0.f, a01 = 0.f, a10 = 0.f, a11 = 0.f;
    #pragma unroll
    for (int c = 0; c < CC; c++) {
        float x0 = sc[ib][c];
        float x1 = sc[ib + 16][c];
        float y0 = sp[jb][c];
        float y1 = sp[jb + 16][c];
        a00 += x0 * y0;
        a01 += x0 * y1;
        a10 += x1 * y0;
        a11 += x1 * y1;
    }

    float lsum = 0.0f;
    lsum += loss_elem(b, i0 + ib,      j0 + jb,      a00, mask);
    lsum += loss_elem(b, i0 + ib,      j0 + jb + 16, a01, mask);
    lsum += loss_elem(b, i0 + ib + 16, j0 + jb,      a10, mask);
    lsum += loss_elem(b, i0 + ib + 16, j0 + jb + 16, a11, mask);

    // warp reduce
    #pragma unroll
    for (int o = 16; o > 0; o >>= 1)
        lsum += __shfl_xor_sync(0xffffffffu, lsum, o);
    if ((t & 31) == 0) wsum[t >> 5] = lsum;
    __syncthreads();
    if (t < 8) {
        float v = wsum[t];
        #pragma unroll
        for (int o = 4; o > 0; o >>= 1)
            v += __shfl_xor_sync(0xffu, v, o);
        if (t == 0) atomicAdd(&g_acc, (double)v);
    }
}

__global__ void finalize_kernel(float* __restrict__ out)
{
    const double denom = (double)BB * (double)KK * (double)KK;  // 2,000,000
    out[0] = (float)(g_acc / denom);
    g_acc = 0.0;  // reset for next (graph-replayed) invocation
}

extern "C" void kernel_launch(void* const* d_in, const int* in_sizes, int n_in,
                              void* d_out, int out_size)
{
    const float* cur_reid = (const float*)d_in[0];
    const float* pre_reid = (const float*)d_in[1];
    const void*  cur_inds = d_in[2];
    const void*  pre_inds = d_in[3];
    const void*  cur_cir  = d_in[4];
    const void*  pre_cir  = d_in[5];
    const int*   mask     = (const int*)d_in[6];
    float* out = (float*)d_out;

    detect_kernel<<<1, 32>>>((const long long*)cur_inds);

    int total = BB * KK * CC;
    gather_kernel<<<(total + 255) / 256, 256>>>(cur_reid, pre_reid,
                                                cur_inds, pre_inds,
                                                cur_cir, pre_cir, mask);

    dim3 grid(NTILE, NTILE, BB);
    loss_kernel<<<grid, 256>>>(mask);

    finalize_kernel<<<1, 1>>>(out);
}

// round 2
// speedup vs baseline: 1.2436x; 1.2436x over previous
#include <cuda_runtime.h>
#include <cstdint>

#define BB 8
#define CC 64
#define HWSZ (152 * 272)     // 41344
#define KK 500
#define KT 64                // output tile edge
#define NT 8                 // ceil(500/64)
#define NBLOCKS (NT * NT * BB)
#define SST 68               // smem row stride (floats): 16B-aligned rows, low-conflict

#define ALPHA 0.25f
#define PROB_MIN 1e-4f

// Scratch (no allocations allowed)
__device__ float    g_cur[BB * KK * CC];   // [B,K,C] gathered
__device__ float    g_pre[BB * KK * CC];
__device__ double   g_acc   = 0.0;
__device__ unsigned g_count = 0;

// ---------------------------------------------------------------------------
// Gather with inline int64/int32 detection (JAX x64 ambiguity).
// Warp 0 of each block probes the first 32 int64-interpreted values of
// cur_inds: if the data were int32, hi-words (= other random indices) would
// make values >= 2^32 with probability 1 - (1/41344)^32 ~ 1.
// ---------------------------------------------------------------------------
__global__ __launch_bounds__(256)
void gather_kernel(const float* __restrict__ cur_reid,
                   const float* __restrict__ pre_reid,
                   const void*  __restrict__ cur_inds,
                   const void*  __restrict__ pre_inds,
                   const void*  __restrict__ cur_cir,
                   const void*  __restrict__ pre_cir,
                   const int*   __restrict__ mask)
{
    __shared__ int s64;
    if (threadIdx.x < 32) {
        long long v = ((const long long*)cur_inds)[threadIdx.x];
        unsigned bad = __ballot_sync(0xffffffffu,
                                     (v < 0) || (v >= (long long)HWSZ));
        if (threadIdx.x == 0) s64 = (bad == 0);
    }
    __syncthreads();

    int tid = blockIdx.x * 256 + threadIdx.x;
    if (tid >= BB * KK * CC) return;
    int c  = tid & (CC - 1);
    int bk = tid >> 6;
    int b  = bk / KK;

    int m = mask[bk];
    int ic, ip;
    if (s64) {
        ic = (int)(m ? ((const long long*)cur_inds)[bk]
                     : ((const long long*)cur_cir)[bk]);
        ip = (int)(m ? ((const long long*)pre_inds)[bk]
                     : ((const long long*)pre_cir)[bk]);
    } else {
        ic = m ? ((const int*)cur_inds)[bk] : ((const int*)cur_cir)[bk];
        ip = m ? ((const int*)pre_inds)[bk] : ((const int*)pre_cir)[bk];
    }

    size_t base = ((size_t)b * CC + c) * (size_t)HWSZ;
    g_cur[tid] = cur_reid[base + ic];
    g_pre[tid] = pre_reid[base + ip];
}

// ---------------------------------------------------------------------------
// Fused GEMM (cur @ pre^T) + sigmoid + focal loss + full reduction + finalize.
// 64x64 tile / block, 256 threads, 4x4 strided register micro-tile, float4 LDS.
// Last block to finish writes the mean and resets scratch (graph-replay safe).
// ---------------------------------------------------------------------------
__device__ __forceinline__ float loss_elem(int b, int i, int j, float dot,
                                           const int* __restrict__ mask)
{
    if (i >= KK || j >= KK) return 0.0f;
    float s = 1.0f / (1.0f + __expf(-dot));
    bool gt = (i == j) && (mask[b * KK + i] != 0);
    float p = gt ? s : (1.0f - s);
    p = fminf(fmaxf(p, PROB_MIN), 1.0f);
    float a = gt ? ALPHA : (1.0f - ALPHA);
    float omp = 1.0f - p;
    return -a * omp * omp * __logf(p);
}

__global__ __launch_bounds__(256)
void loss_kernel(const int* __restrict__ mask, float* __restrict__ out)
{
    __shared__ float sc[KT][SST];
    __shared__ float sp[KT][SST];
    __shared__ float wsum[8];

    int b  = blockIdx.z;
    int i0 = blockIdx.y * KT;
    int j0 = blockIdx.x * KT;
    int t  = threadIdx.x;

    // Load both 64x64 tiles as float4, zero-fill rows >= 500.
    #pragma unroll
    for (int k = 0; k < 4; k++) {
        int id = t + 256 * k;          // 0..1023
        int r  = id >> 4;              // row 0..63
        int c4 = (id & 15) << 2;       // col 0,4,...,60
        float4 vc = make_float4(0.f, 0.f, 0.f, 0.f);
        float4 vp = vc;
        if (i0 + r < KK)
            vc = *(const float4*)&g_cur[((size_t)b * KK + i0 + r) * CC + c4];
        if (j0 + r < KK)
            vp = *(const float4*)&g_pre[((size_t)b * KK + j0 + r) * CC + c4];
        *(float4*)&sc[r][c4] = vc;
        *(float4*)&sp[r][c4] = vp;
    }
    __syncthreads();

    int ib = t & 15;    // i rows: ib + 16u
    int jb = t >> 4;    // j rows: jb + 16v

    float acc[4][4] = {};
    #pragma unroll
    for (int cc = 0; cc < 16; cc++) {
        float4 x[4], y[4];
        #pragma unroll
        for (int u = 0; u < 4; u++) x[u] = *(const float4*)&sc[ib + 16 * u][cc << 2];
        #pragma unroll
        for (int v = 0; v < 4; v++) y[v] = *(const float4*)&sp[jb + 16 * v][cc << 2];
        #pragma unroll
        for (int u = 0; u < 4; u++)
            #pragma unroll
            for (int v = 0; v < 4; v++)
                acc[u][v] += x[u].x * y[v].x + x[u].y * y[v].y
                           + x[u].z * y[v].z + x[u].w * y[v].w;
    }

    float lsum = 0.0f;
    #pragma unroll
    for (int u = 0; u < 4; u++)
        #pragma unroll
        for (int v = 0; v < 4; v++)
            lsum += loss_elem(b, i0 + ib + 16 * u, j0 + jb + 16 * v,
                              acc[u][v], mask);

    // warp reduce
    #pragma unroll
    for (int o = 16; o > 0; o >>= 1)
        lsum += __shfl_xor_sync(0xffffffffu, lsum, o);
    if ((t & 31) == 0) wsum[t >> 5] = lsum;
    __syncthreads();

    if (t == 0) {
        float v = 0.f;
        #pragma unroll
        for (int w = 0; w < 8; w++) v += wsum[w];
        atomicAdd(&g_acc, (double)v);
        __threadfence();
        unsigned old = atomicAdd(&g_count, 1u);
        if (old == NBLOCKS - 1) {
            // All blocks' g_acc adds are ordered before their counter bump.
            double tot = atomicAdd(&g_acc, 0.0);
            out[0] = (float)(tot / ((double)BB * KK * KK));
            g_acc   = 0.0;     // reset for next graph replay (no racers left)
            __threadfence();
            g_count = 0u;
        }
    }
}

extern "C" void kernel_launch(void* const* d_in, const int* in_sizes, int n_in,
                              void* d_out, int out_size)
{
    const float* cur_reid = (const float*)d_in[0];
    const float* pre_reid = (const float*)d_in[1];
    const void*  cur_inds = d_in[2];
    const void*  pre_inds = d_in[3];
    const void*  cur_cir  = d_in[4];
    const void*  pre_cir  = d_in[5];
    const int*   mask     = (const int*)d_in[6];
    float* out = (float*)d_out;

    int total = BB * KK * CC;
    gather_kernel<<<(total + 255) / 256, 256>>>(cur_reid, pre_reid,
                                                cur_inds, pre_inds,
                                                cur_cir, pre_cir, mask);

    dim3 grid(NT, NT, BB);
    loss_kernel<<<grid, 256>>>(mask, out);
}

// round 4
// speedup vs baseline: 1.6470x; 1.3243x over previous
#include <cuda_runtime.h>
#include <cuda_bf16.h>
#include <cstdint>

#define BB 8
#define CC 64
#define HWSZ (152 * 272)     // 41344
#define KK 500
#define KPAD 512
#define NBLOCKS (4 * 4 * BB) // 128 loss blocks

#define ALPHA 0.25f
#define PROB_MIN 1e-4f

// Scratch (no allocations allowed)
__device__ __nv_bfloat16 g_curb[BB * KPAD * CC];  // [B,512,64], rows>=500 zero
__device__ __nv_bfloat16 g_preb[BB * KPAD * CC];
__device__ double   g_acc   = 0.0;
__device__ unsigned g_count = 0;

__device__ __forceinline__ uint32_t smem_u32(const void* p) {
    uint32_t a;
    asm("{ .reg .u64 t; cvta.to.shared.u64 t, %1; cvt.u32.u64 %0, t; }"
        : "=r"(a) : "l"(p));
    return a;
}
__device__ __forceinline__ void ldsm_x4(uint32_t& r0, uint32_t& r1,
                                        uint32_t& r2, uint32_t& r3,
                                        uint32_t addr) {
    asm volatile("ldmatrix.sync.aligned.m8n8.x4.shared.b16 {%0,%1,%2,%3}, [%4];"
                 : "=r"(r0), "=r"(r1), "=r"(r2), "=r"(r3) : "r"(addr));
}
__device__ __forceinline__ void ldsm_x2(uint32_t& r0, uint32_t& r1,
                                        uint32_t addr) {
    asm volatile("ldmatrix.sync.aligned.m8n8.x2.shared.b16 {%0,%1}, [%2];"
                 : "=r"(r0), "=r"(r1) : "r"(addr));
}
__device__ __forceinline__ void mma_16816(float* c, const uint32_t* a,
                                          const uint32_t* b) {
    asm volatile(
        "mma.sync.aligned.m16n8k16.row.col.f32.bf16.bf16.f32 "
        "{%0,%1,%2,%3}, {%4,%5,%6,%7}, {%8,%9}, {%0,%1,%2,%3};"
        : "+f"(c[0]), "+f"(c[1]), "+f"(c[2]), "+f"(c[3])
        : "r"(a[0]), "r"(a[1]), "r"(a[2]), "r"(a[3]), "r"(b[0]), "r"(b[1]));
}

// ---------------------------------------------------------------------------
// Gather + bf16 convert, with inline int64/int32 index-dtype detection.
// ---------------------------------------------------------------------------
__global__ __launch_bounds__(256)
void gather_kernel(const float* __restrict__ cur_reid,
                   const float* __restrict__ pre_reid,
                   const void*  __restrict__ cur_inds,
                   const void*  __restrict__ pre_inds,
                   const void*  __restrict__ cur_cir,
                   const void*  __restrict__ pre_cir,
                   const int*   __restrict__ mask)
{
    __shared__ int s64;
    if (threadIdx.x < 32) {
        long long v = ((const long long*)cur_inds)[threadIdx.x];
        unsigned bad = __ballot_sync(0xffffffffu,
                                     (v < 0) || (v >= (long long)HWSZ));
        if (threadIdx.x == 0) s64 = (bad == 0);
    }
    __syncthreads();

    int tid = blockIdx.x * 256 + threadIdx.x;
    if (tid >= BB * KPAD * CC) return;
    int c   = tid & (CC - 1);
    int bk  = tid >> 6;            // b*512 + row
    int b   = bk >> 9;
    int row = bk & (KPAD - 1);

    if (row >= KK) {               // zero padding rows
        g_curb[tid] = __float2bfloat16(0.0f);
        g_preb[tid] = __float2bfloat16(0.0f);
        return;
    }
    int mk = b * KK + row;
    int m  = mask[mk];
    int ic, ip;
    if (s64) {
        ic = (int)(m ? ((const long long*)cur_inds)[mk]
                     : ((const long long*)cur_cir)[mk]);
        ip = (int)(m ? ((const long long*)pre_inds)[mk]
                     : ((const long long*)pre_cir)[mk]);
    } else {
        ic = m ? ((const int*)cur_inds)[mk] : ((const int*)cur_cir)[mk];
        ip = m ? ((const int*)pre_inds)[mk] : ((const int*)pre_cir)[mk];
    }
    size_t base = ((size_t)b * CC + c) * (size_t)HWSZ;
    g_curb[tid] = __float2bfloat16(cur_reid[base + ic]);
    g_preb[tid] = __float2bfloat16(pre_reid[base + ip]);
}

// ---------------------------------------------------------------------------
// HMMA loss kernel: 128x128 tile/block (grid 4x4x8), 8 warps of 64x32 tiles,
// mma.sync m16n8k16 bf16. Loss computed directly on register fragments.
// ---------------------------------------------------------------------------
__global__ __launch_bounds__(256)
void loss_kernel(const int* __restrict__ mask, float* __restrict__ out)
{
    __shared__ __align__(128) uint8_t smA[128 * 128]; // 128 rows x 64 bf16
    __shared__ __align__(128) uint8_t smB[128 * 128];
    __shared__ float wsum[8];

    int t   = threadIdx.x;
    int w   = t >> 5;
    int lid = t & 31;
    int b   = blockIdx.z;
    int i0  = blockIdx.y * 128;
    int j0  = blockIdx.x * 128;

    // Stage tiles: 16B chunks, chunk' = chunk ^ (row & 7)  (conflict-free LDSM)
    const uint4* srcA = (const uint4*)(g_curb + ((size_t)b * KPAD + i0) * CC);
    const uint4* srcB = (const uint4*)(g_preb + ((size_t)b * KPAD + j0) * CC);
    #pragma unroll
    for (int u = t; u < 1024; u += 256) {
        int r = u >> 3;                       // row 0..127
        int c = u & 7;                        // chunk 0..7
        int sw = (r << 7) + ((c ^ (r & 7)) << 4);
        *(uint4*)(smA + sw) = srcA[u];
        *(uint4*)(smB + sw) = srcB[u];
    }
    __syncthreads();

    uint32_t baseA = smem_u32(smA);
    uint32_t baseB = smem_u32(smB);

    int wm = w & 1;        // 0..1 -> 64 rows each
    int wn = w >> 1;       // 0..3 -> 32 cols each

    float acc[4][4][4] = {};   // [mfrag][nfrag][reg]

    #pragma unroll
    for (int ks = 0; ks < 4; ks++) {
        int kc = ks * 2;   // 16B chunk index of this k-step

        uint32_t a[4][4];
        #pragma unroll
        for (int fm = 0; fm < 4; fm++) {
            int row = wm * 64 + fm * 16 + (lid & 7) + ((lid >> 3) & 1) * 8;
            int ch  = kc + (lid >> 4);
            uint32_t addr = baseA + (row << 7) + ((ch ^ (row & 7)) << 4);
            ldsm_x4(a[fm][0], a[fm][1], a[fm][2], a[fm][3], addr);
        }
        uint32_t bfr[4][2];
        #pragma unroll
        for (int fn = 0; fn < 4; fn++) {
            int l8  = lid & 15;
            int row = wn * 32 + fn * 8 + (l8 & 7);
            int ch  = kc + (l8 >> 3);
            uint32_t addr = baseB + (row << 7) + ((ch ^ (row & 7)) << 4);
            ldsm_x2(bfr[fn][0], bfr[fn][1], addr);
        }
        #pragma unroll
        for (int fm = 0; fm < 4; fm++)
            #pragma unroll
            for (int fn = 0; fn < 4; fn++)
                mma_16816(acc[fm][fn], a[fm], bfr[fn]);
    }

    // Epilogue: loss directly on fragments.
    // c0:(i, j) c1:(i, j+1) c2:(i+8, j) c3:(i+8, j+1),
    // i = i0+wm*64+fm*16+gid, j = j0+wn*32+fn*8+2*tig
    int gid = lid >> 2;
    int tig = lid & 3;
    float lsum = 0.0f;

    #pragma unroll
    for (int fm = 0; fm < 4; fm++) {
        #pragma unroll
        for (int fn = 0; fn < 4; fn++) {
            int ibase = i0 + wm * 64 + fm * 16 + gid;
            int jbase = j0 + wn * 32 + fn * 8 + 2 * tig;
            #pragma unroll
            for (int rg = 0; rg < 4; rg++) {
                int i = ibase + (rg >> 1) * 8;
                int j = jbase + (rg & 1);
                if (i < KK && j < KK) {
                    float x  = acc[fm][fn][rg];
                    float e  = __expf(x);
                    float r  = __fdividef(1.0f, 1.0f + e);  // 1 - sigmoid(x)
                    bool  gt = (i == j) && (mask[b * KK + i] != 0);
                    float p  = gt ? (1.0f - r) : r;
                    p = fmaxf(p, PROB_MIN);
                    float al  = gt ? ALPHA : (1.0f - ALPHA);
                    float omp = 1.0f - p;
                    lsum -= al * omp * omp * __logf(p);
                }
            }
        }
    }

    // Block reduction -> global atomic -> last-block finalize.
    #pragma unroll
    for (int o = 16; o > 0; o >>= 1)
        lsum += __shfl_xor_sync(0xffffffffu, lsum, o);
    if (lid == 0) wsum[w] = lsum;
    __syncthreads();

    if (t == 0) {
        float v = 0.f;
        #pragma unroll
        for (int k = 0; k < 8; k++) v += wsum[k];
        atomicAdd(&g_acc, (double)v);
        __threadfence();
        unsigned old = atomicAdd(&g_count, 1u);
        if (old == NBLOCKS - 1) {
            double tot = atomicAdd(&g_acc, 0.0);
            out[0] = (float)(tot / ((double)BB * KK * KK));
            g_acc = 0.0;            // reset for next graph replay
            __threadfence();
            g_count = 0u;
        }
    }
}

extern "C" void kernel_launch(void* const* d_in, const int* in_sizes, int n_in,
                              void* d_out, int out_size)
{
    const float* cur_reid = (const float*)d_in[0];
    const float* pre_reid = (const float*)d_in[1];
    const void*  cur_inds = d_in[2];
    const void*  pre_inds = d_in[3];
    const void*  cur_cir  = d_in[4];
    const void*  pre_cir  = d_in[5];
    const int*   mask     = (const int*)d_in[6];
    float* out = (float*)d_out;

    int total = BB * KPAD * CC;
    gather_kernel<<<(total + 255) / 256, 256>>>(cur_reid, pre_reid,
                                                cur_inds, pre_inds,
                                                cur_cir, pre_cir, mask);

    dim3 grid(4, 4, BB);
    loss_kernel<<<grid, 256>>>(mask, out);
}

// round 5
// speedup vs baseline: 2.1013x; 1.2759x over previous
#include <cuda_runtime.h>
#include <cuda_bf16.h>
#include <cstdint>

#define BB 8
#define CC 64
#define HWSZ (152 * 272)     // 41344
#define KK 500
#define KPAD 512
#define NBLOCKS (8 * 8 * BB) // 512 loss blocks

#define ALPHA 0.25f
#define PROB_MIN 1e-4f

// Scratch (no allocations allowed)
__device__ __nv_bfloat16 g_curb[BB * KPAD * CC];  // [B,512,64], rows>=500 zero
__device__ __nv_bfloat16 g_preb[BB * KPAD * CC];
__device__ double   g_acc   = 0.0;
__device__ unsigned g_count = 0;

__device__ __forceinline__ uint32_t smem_u32(const void* p) {
    uint32_t a;
    asm("{ .reg .u64 t; cvta.to.shared.u64 t, %1; cvt.u32.u64 %0, t; }"
        : "=r"(a) : "l"(p));
    return a;
}
__device__ __forceinline__ void ldsm_x4(uint32_t& r0, uint32_t& r1,
                                        uint32_t& r2, uint32_t& r3,
                                        uint32_t addr) {
    asm volatile("ldmatrix.sync.aligned.m8n8.x4.shared.b16 {%0,%1,%2,%3}, [%4];"
                 : "=r"(r0), "=r"(r1), "=r"(r2), "=r"(r3) : "r"(addr));
}
__device__ __forceinline__ void ldsm_x2(uint32_t& r0, uint32_t& r1,
                                        uint32_t addr) {
    asm volatile("ldmatrix.sync.aligned.m8n8.x2.shared.b16 {%0,%1}, [%2];"
                 : "=r"(r0), "=r"(r1) : "r"(addr));
}
__device__ __forceinline__ void mma_16816(float* c, const uint32_t* a,
                                          const uint32_t* b) {
    asm volatile(
        "mma.sync.aligned.m16n8k16.row.col.f32.bf16.bf16.f32 "
        "{%0,%1,%2,%3}, {%4,%5,%6,%7}, {%8,%9}, {%0,%1,%2,%3};"
        : "+f"(c[0]), "+f"(c[1]), "+f"(c[2]), "+f"(c[3])
        : "r"(a[0]), "r"(a[1]), "r"(a[2]), "r"(a[3]), "r"(b[0]), "r"(b[1]));
}

// Off-diagonal, in-bounds loss element (gt always 0, alpha_t = 0.75).
__device__ __forceinline__ float loss_fast(float x) {
    float e   = __expf(x);
    float r   = __fdividef(1.0f, 1.0f + e);   // 1 - sigmoid(x)
    float p   = fmaxf(r, PROB_MIN);
    float omp = 1.0f - p;
    return -(1.0f - ALPHA) * omp * omp * __logf(p);
}
// General element.
__device__ __forceinline__ float loss_gen(float x, bool gt) {
    float e   = __expf(x);
    float r   = __fdividef(1.0f, 1.0f + e);
    float p   = gt ? (1.0f - r) : r;
    p = fmaxf(p, PROB_MIN);
    float a   = gt ? ALPHA : (1.0f - ALPHA);
    float omp = 1.0f - p;
    return -a * omp * omp * __logf(p);
}

// ---------------------------------------------------------------------------
// Gather + bf16 convert. 2 channels/thread, bf16x2 packed stores.
// Inline int64/int32 index-dtype detection (JAX x64 ambiguity).
// ---------------------------------------------------------------------------
__global__ __launch_bounds__(256)
void gather_kernel(const float* __restrict__ cur_reid,
                   const float* __restrict__ pre_reid,
                   const void*  __restrict__ cur_inds,
                   const void*  __restrict__ pre_inds,
                   const void*  __restrict__ cur_cir,
                   const void*  __restrict__ pre_cir,
                   const int*   __restrict__ mask)
{
    __shared__ int s64;
    if (threadIdx.x < 32) {
        long long v = ((const long long*)cur_inds)[threadIdx.x];
        unsigned bad = __ballot_sync(0xffffffffu,
                                     (v < 0) || (v >= (long long)HWSZ));
        if (threadIdx.x == 0) s64 = (bad == 0);
    }
    __syncthreads();

    int tid = blockIdx.x * 256 + threadIdx.x;     // one bf16x2 pair each
    if (tid >= BB * KPAD * 32) return;
    int c2  = tid & 31;            // channel pair: c = 2*c2, 2*c2+1
    int bk  = tid >> 5;            // b*512 + row
    int b   = bk >> 9;
    int row = bk & (KPAD - 1);

    __nv_bfloat162* dstC = (__nv_bfloat162*)g_curb;
    __nv_bfloat162* dstP = (__nv_bfloat162*)g_preb;

    if (row >= KK) {
        __nv_bfloat162 z;
        z.x = __float2bfloat16(0.0f); z.y = z.x;
        dstC[tid] = z;
        dstP[tid] = z;
        return;
    }
    int mk = b * KK + row;
    int m  = mask[mk];
    int ic, ip;
    if (s64) {
        ic = (int)(m ? ((const long long*)cur_inds)[mk]
                     : ((const long long*)cur_cir)[mk]);
        ip = (int)(m ? ((const long long*)pre_inds)[mk]
                     : ((const long long*)pre_cir)[mk]);
    } else {
        ic = m ? ((const int*)cur_inds)[mk] : ((const int*)cur_cir)[mk];
        ip = m ? ((const int*)pre_inds)[mk] : ((const int*)pre_cir)[mk];
    }
    size_t base = ((size_t)b * CC + 2 * c2) * (size_t)HWSZ;
    float c0 = cur_reid[base + ic];
    float c1 = cur_reid[base + HWSZ + ic];
    float p0 = pre_reid[base + ip];
    float p1 = pre_reid[base + HWSZ + ip];
    __nv_bfloat162 vc, vp;
    vc.x = __float2bfloat16(c0); vc.y = __float2bfloat16(c1);
    vp.x = __float2bfloat16(p0); vp.y = __float2bfloat16(p1);
    dstC[tid] = vc;
    dstP[tid] = vp;
}

// ---------------------------------------------------------------------------
// HMMA loss kernel: 64x64 tile/block, grid (8,8,8)=512 blocks, 8 warps of
// 32x16 tiles, mma.sync m16n8k16 bf16. Loss computed on register fragments.
// ---------------------------------------------------------------------------
__global__ __launch_bounds__(256)
void loss_kernel(const int* __restrict__ mask, float* __restrict__ out)
{
    __shared__ __align__(128) uint8_t smA[64 * 128]; // 64 rows x 64 bf16
    __shared__ __align__(128) uint8_t smB[64 * 128];
    __shared__ float wsum[8];

    int t   = threadIdx.x;
    int w   = t >> 5;
    int lid = t & 31;
    int b   = blockIdx.z;
    int it  = blockIdx.y;
    int jt  = blockIdx.x;
    int i0  = it * 64;
    int j0  = jt * 64;

    // Stage tiles: 512 x 16B each; swizzle chunk ^= (row & 7).
    const uint4* srcA = (const uint4*)(g_curb + ((size_t)b * KPAD + i0) * CC);
    const uint4* srcB = (const uint4*)(g_preb + ((size_t)b * KPAD + j0) * CC);
    #pragma unroll
    for (int k = 0; k < 2; k++) {
        int u  = t + 256 * k;                 // 0..511
        int r  = u >> 3;                      // row 0..63
        int c  = u & 7;
        int sw = (r << 7) + ((c ^ (r & 7)) << 4);
        *(uint4*)(smA + sw) = srcA[u];
        *(uint4*)(smB + sw) = srcB[u];
    }
    __syncthreads();

    uint32_t baseA = smem_u32(smA);
    uint32_t baseB = smem_u32(smB);

    int wm = w & 1;        // 2 x 32 rows
    int wn = w >> 1;       // 4 x 16 cols

    float acc[2][2][4] = {};   // [fm][fn][reg]

    #pragma unroll
    for (int ks = 0; ks < 4; ks++) {
        int kc = ks * 2;

        uint32_t a[2][4];
        #pragma unroll
        for (int fm = 0; fm < 2; fm++) {
            int row = wm * 32 + fm * 16 + (lid & 7) + ((lid >> 3) & 1) * 8;
            int ch  = kc + (lid >> 4);
            uint32_t addr = baseA + (row << 7) + ((ch ^ (row & 7)) << 4);
            ldsm_x4(a[fm][0], a[fm][1], a[fm][2], a[fm][3], addr);
        }
        uint32_t bf[2][2];
        #pragma unroll
        for (int fn = 0; fn < 2; fn++) {
            int l8  = lid & 15;
            int row = wn * 16 + fn * 8 + (l8 & 7);
            int ch  = kc + (l8 >> 3);
            uint32_t addr = baseB + (row << 7) + ((ch ^ (row & 7)) << 4);
            ldsm_x2(bf[fn][0], bf[fn][1], addr);
        }
        #pragma unroll
        for (int fm = 0; fm < 2; fm++)
            #pragma unroll
            for (int fn = 0; fn < 2; fn++)
                mma_16816(acc[fm][fn], a[fm], bf[fn]);
    }

    // Epilogue on fragments:
    // c0:(i,j) c1:(i,j+1) c2:(i+8,j) c3:(i+8,j+1);
    // i = i0+wm*32+fm*16+gid(+8), j = j0+wn*16+fn*8+2*tig(+1)
    int gid = lid >> 2;
    int tig = lid & 3;
    float lsum = 0.0f;

    bool interior = (it < 7) && (jt < 7);
    bool diag     = (it == jt);

    if (interior && !diag) {
        // Fast path: no bounds checks, gt never true.
        #pragma unroll
        for (int fm = 0; fm < 2; fm++)
            #pragma unroll
            for (int fn = 0; fn < 2; fn++)
                #pragma unroll
                for (int rg = 0; rg < 4; rg++)
                    lsum += loss_fast(acc[fm][fn][rg]);
    } else {
        #pragma unroll
        for (int fm = 0; fm < 2; fm++) {
            int ib = i0 + wm * 32 + fm * 16 + gid;
            int m0 = (diag && ib     < KK) ? mask[b * KK + ib]     : 0;
            int m8 = (diag && ib + 8 < KK) ? mask[b * KK + ib + 8] : 0;
            #pragma unroll
            for (int fn = 0; fn < 2; fn++) {
                int jb = j0 + wn * 16 + fn * 8 + 2 * tig;
                #pragma unroll
                for (int rg = 0; rg < 4; rg++) {
                    int i = ib + (rg >> 1) * 8;
                    int j = jb + (rg & 1);
                    if (i < KK && j < KK) {
                        bool gt = diag && (i == j) &&
                                  (((rg >> 1) ? m8 : m0) != 0);
                        lsum += loss_gen(acc[fm][fn][rg], gt);
                    }
                }
            }
        }
    }

    // Block reduction -> global atomic -> last-block finalize.
    #pragma unroll
    for (int o = 16; o > 0; o >>= 1)
        lsum += __shfl_xor_sync(0xffffffffu, lsum, o);
    if (lid == 0) wsum[w] = lsum;
    __syncthreads();

    if (t == 0) {
        float v = 0.f;
        #pragma unroll
        for (int k = 0; k < 8; k++) v += wsum[k];
        atomicAdd(&g_acc, (double)v);
        __threadfence();
        unsigned old = atomicAdd(&g_count, 1u);
        if (old == NBLOCKS - 1) {
            double tot = atomicAdd(&g_acc, 0.0);
            out[0] = (float)(tot / ((double)BB * KK * KK));
            g_acc = 0.0;            // reset for next graph replay
            __threadfence();
            g_count = 0u;
        }
    }
}

extern "C" void kernel_launch(void* const* d_in, const int* in_sizes, int n_in,
                              void* d_out, int out_size)
{
    const float* cur_reid = (const float*)d_in[0];
    const float* pre_reid = (const float*)d_in[1];
    const void*  cur_inds = d_in[2];
    const void*  pre_inds = d_in[3];
    const void*  cur_cir  = d_in[4];
    const void*  pre_cir  = d_in[5];
    const int*   mask     = (const int*)d_in[6];
    float* out = (float*)d_out;

    int totalPairs = BB * KPAD * 32;
    gather_kernel<<<(totalPairs + 255) / 256, 256>>>(cur_reid, pre_reid,
                                                     cur_inds, pre_inds,
                                                     cur_cir, pre_cir, mask);

    dim3 grid(8, 8, BB);
    loss_kernel<<<grid, 256>>>(mask, out);
}